// round 16
// baseline (speedup 1.0000x reference)
#include <cuda_runtime.h>
#include <stdint.h>

// ---------------------------------------------------------------------------
// AdaptiveUnpooling v16:
//   - edge stores the OTHER NODE ID (register) in g_adj — no pos loads at
//     all inside edge. Gather translates node->pos (broadcast load) before
//     reading the feature row.
//   - packed dual counter: g_cnt = (present_cnt << 16) | total_cnt; missing
//     sources bump total only (no store), present sources get dense slots.
//   - NO miss list: gather runs one warp per node over all N; present-node
//     warps exit uniformly after one broadcast bitmap load.
//   - edge: 64-bit canonical CAS, 32MB table, UB=4, SMEM presence bitmap,
//     lb(256,6), exact-wave 888-block grid.
//   - pre-edge fork: side stream (clear_small -> scatter) || clear_table;
//     joined BEFORE edge.
// ---------------------------------------------------------------------------

#define TAB_BITS 22
#define TAB_SIZE (1u << TAB_BITS)      // 4M slots * 8B = 32MB (L2-resident)
#define MAX_N    131072
#define BM_WORDS (MAX_N / 32)
#define ADJ_DEG  96
#define UB       4
#define EDGE_BLOCKS  888               // 148 SMs * 6 blocks/SM
#define EDGE_THREADS 256

__device__ unsigned long long g_hash[TAB_SIZE];
__device__ unsigned g_cnt[MAX_N];      // (present_cnt << 16) | total_cnt
__device__ int g_pos[MAX_N];
__device__ unsigned g_bitmap[BM_WORDS];
__device__ int g_adj[MAX_N * ADJ_DEG]; // dense present-source NODE IDs

__device__ __forceinline__ uint64_t mix64(uint64_t x) {
    x ^= x >> 33; x *= 0xff51afd7ed558ccdULL;
    x ^= x >> 33; x *= 0xc4ceb9fe1a85ec53ULL;
    x ^= x >> 33;
    return x;
}

__global__ void clear_table_kernel() {
    const int stride = gridDim.x * blockDim.x;
    const int tid = blockIdx.x * blockDim.x + threadIdx.x;
    ulonglong2* h2 = reinterpret_cast<ulonglong2*>(g_hash);
    for (unsigned i = tid; i < TAB_SIZE / 2; i += stride)
        h2[i] = make_ulonglong2(0ULL, 0ULL);
}

__global__ void clear_small_kernel(int N) {
    const int stride = gridDim.x * blockDim.x;
    const int tid = blockIdx.x * blockDim.x + threadIdx.x;
    for (int i = tid; i < N; i += stride) { g_cnt[i] = 0u; g_pos[i] = -1; }
    for (int i = tid; i < BM_WORDS; i += stride) g_bitmap[i] = 0u;
}

// Copy present rows, build pos map and presence bitmap.
__global__ void scatter_kernel(const float4* __restrict__ x4,
                               const int* __restrict__ perm,
                               float4* __restrict__ out4,
                               int P, int Cv) {
    const int gtid = blockIdx.x * blockDim.x + threadIdx.x;
    const int r = gtid / Cv;
    const int c = gtid - r * Cv;
    if (r < P) {
        const int node = perm[r];
        if (c == 0) {
            g_pos[node] = r;
            atomicOr(&g_bitmap[node >> 5], 1u << (node & 31));
        }
        out4[(size_t)node * Cv + c] = x4[(size_t)r * Cv + c];
    }
}

// UB edges per batch; SMEM bitmap presence; register-only adjacency payload.
__global__ void __launch_bounds__(EDGE_THREADS, 6)
edge_kernel(const int* __restrict__ e0,
            const int* __restrict__ e1,
            int E, int N) {
    __shared__ unsigned s_bm[BM_WORDS];
    const int nw = (N + 31) >> 5;
    for (int i = threadIdx.x; i < nw; i += blockDim.x) s_bm[i] = g_bitmap[i];
    __syncthreads();

    const int tid = blockIdx.x * blockDim.x + threadIdx.x;
    const int TOT = gridDim.x * blockDim.x;
    const int step = TOT * UB;

    for (int base = tid; base < E; base += step) {
        int a[UB], b[UB];
        bool act[UB], ma[UB], mb[UB];

        // Phase 1: coalesced edge loads
        #pragma unroll
        for (int k = 0; k < UB; k++) {
            const int j = base + k * TOT;
            const bool v = (j < E);
            act[k] = v;
            a[k] = v ? e0[j] : 0;
            b[k] = v ? e1[j] : 1;
        }

        // Phase 2: presence checks from SMEM bitmap
        #pragma unroll
        for (int k = 0; k < UB; k++) {
            ma[k] = !((s_bm[a[k] >> 5] >> (a[k] & 31)) & 1u);
            mb[k] = !((s_bm[b[k] >> 5] >> (b[k] & 31)) & 1u);
            act[k] = act[k] && (a[k] != b[k]) && (ma[k] || mb[k]);
        }

        // Phase 3: canonical keys + batched first-probe CAS
        unsigned h[UB];
        unsigned long long old[UB];
        #pragma unroll
        for (int k = 0; k < UB; k++) {
            const int lo = min(a[k], b[k]), hi = max(a[k], b[k]);
            const uint64_t key = (uint64_t)lo * (uint64_t)N + (uint64_t)hi + 1ULL;
            h[k] = (unsigned)mix64(key) & (TAB_SIZE - 1);
            old[k] = act[k] ? atomicCAS(&g_hash[h[k]], 0ULL, key) : 1ULL;
        }

        // Phase 4: resolve rare collisions
        bool win[UB];
        #pragma unroll
        for (int k = 0; k < UB; k++) {
            win[k] = false;
            if (act[k]) {
                const int lo = min(a[k], b[k]), hi = max(a[k], b[k]);
                const uint64_t key = (uint64_t)lo * (uint64_t)N + (uint64_t)hi + 1ULL;
                unsigned long long o = old[k];
                unsigned hh = h[k];
                while (o != 0ULL && o != key) {
                    hh = (hh + 1) & (TAB_SIZE - 1);
                    o = atomicCAS(&g_hash[hh], 0ULL, key);
                }
                win[k] = (o == 0ULL);
            }
        }

        // Phase 5: packed-counter bump; store other NODE ID (register) for
        // present sources. Zero loads in this phase.
        #pragma unroll
        for (int k = 0; k < UB; k++) {
            if (win[k]) {
                if (ma[k]) {
                    const bool pres = !mb[k];
                    const unsigned o = atomicAdd(&g_cnt[a[k]],
                                                 pres ? 0x10001u : 1u);
                    if (pres) {
                        const int slot = (int)(o >> 16);
                        if (slot < ADJ_DEG)
                            g_adj[a[k] * ADJ_DEG + slot] = b[k];
                    }
                }
                if (mb[k]) {
                    const bool pres = !ma[k];
                    const unsigned o = atomicAdd(&g_cnt[b[k]],
                                                 pres ? 0x10001u : 1u);
                    if (pres) {
                        const int slot = (int)(o >> 16);
                        if (slot < ADJ_DEG)
                            g_adj[b[k] * ADJ_DEG + slot] = a[k];
                    }
                }
            }
        }
    }
}

// One warp per node (all N). Present nodes exit after one broadcast bitmap
// load. Missing: two parallel adjacency chains, node->pos translation,
// register accumulate, single non-atomic store of the mean.
__global__ void gather_kernel(const float4* __restrict__ xa4,
                              float4* __restrict__ out4,
                              int N, int Cv) {
    const int lane = threadIdx.x & 31;
    const int li   = lane & 15;
    const int half = lane >> 4;
    const int t = (blockIdx.x * blockDim.x + threadIdx.x) >> 5;
    if (t >= N) return;
    if ((g_bitmap[t >> 5] >> (t & 31)) & 1u) return;   // present: uniform exit

    const unsigned cw = g_cnt[t];
    const int total = (int)(cw & 0xFFFFu);
    const int m     = min((int)(cw >> 16), ADJ_DEG);
    const int4* row = reinterpret_cast<const int4*>(&g_adj[t * ADJ_DEG]);

    float4 acc = make_float4(0.f, 0.f, 0.f, 0.f);
    for (int g = half; g * 4 < m; g += 2) {
        const int4 q = row[g];
        const int bse = g * 4;
        // translate node ids -> pooled rows (broadcast loads)
        const int p0 = g_pos[q.x];
        const int p1 = (bse + 1 < m) ? g_pos[q.y] : 0;
        const int p2 = (bse + 2 < m) ? g_pos[q.z] : 0;
        const int p3 = (bse + 3 < m) ? g_pos[q.w] : 0;
        float4 v0 = xa4[(size_t)p0 * Cv + li];
        float4 v1 = make_float4(0.f,0.f,0.f,0.f), v2 = v1, v3 = v1;
        if (bse + 1 < m) v1 = xa4[(size_t)p1 * Cv + li];
        if (bse + 2 < m) v2 = xa4[(size_t)p2 * Cv + li];
        if (bse + 3 < m) v3 = xa4[(size_t)p3 * Cv + li];
        acc.x += (v0.x + v1.x) + (v2.x + v3.x);
        acc.y += (v0.y + v1.y) + (v2.y + v3.y);
        acc.z += (v0.z + v1.z) + (v2.z + v3.z);
        acc.w += (v0.w + v1.w) + (v2.w + v3.w);
    }

    acc.x += __shfl_xor_sync(0xffffffffu, acc.x, 16);
    acc.y += __shfl_xor_sync(0xffffffffu, acc.y, 16);
    acc.z += __shfl_xor_sync(0xffffffffu, acc.z, 16);
    acc.w += __shfl_xor_sync(0xffffffffu, acc.w, 16);

    if (half == 0) {
        const float inv = (total > 0) ? 1.0f / (float)total : 0.0f;
        acc.x *= inv; acc.y *= inv; acc.z *= inv; acc.w *= inv;
        out4[(size_t)t * Cv + li] = acc;
    }
}

extern "C" void kernel_launch(void* const* d_in, const int* in_sizes, int n_in,
                              void* d_out, int out_size) {
    const float* xa   = (const float*)d_in[0];   // [P, C] f32
    const int*   perm = (const int*)d_in[1];     // [P]
    const int*   ei   = (const int*)d_in[2];     // [2, E]
    (void)n_in;

    const int P  = in_sizes[1];
    const int C  = in_sizes[0] / P;              // 64
    const int Cv = C / 4;                        // 16
    const int E  = in_sizes[2] / 2;
    const int N  = out_size / C;                 // 100000
    float* out = (float*)d_out;

    // One-time host resources (no device memory).
    static cudaStream_t s1 = nullptr;
    static cudaEvent_t evFork = nullptr, evSide = nullptr;
    if (s1 == nullptr) {
        cudaStreamCreateWithFlags(&s1, cudaStreamNonBlocking);
        cudaEventCreateWithFlags(&evFork, cudaEventDisableTiming);
        cudaEventCreateWithFlags(&evSide, cudaEventDisableTiming);
    }

    // Fork: side chain (clear_small -> scatter) || main clear_table.
    // Joined BEFORE edge: nothing ever co-runs with the edge kernel.
    cudaEventRecord(evFork, 0);
    cudaStreamWaitEvent(s1, evFork, 0);

    clear_small_kernel<<<256, 256, 0, s1>>>(N);
    {
        const int work = P * Cv;
        scatter_kernel<<<(work + 255) / 256, 256, 0, s1>>>(
            (const float4*)xa, perm, (float4*)out, P, Cv);
    }
    cudaEventRecord(evSide, s1);

    clear_table_kernel<<<2048, 256>>>();

    cudaStreamWaitEvent(0, evSide, 0);
    edge_kernel<<<EDGE_BLOCKS, EDGE_THREADS>>>(ei, ei + E, E, N);

    {
        const long long work = (long long)N * 32;    // one warp per node
        const int blocks = (int)((work + 255) / 256);
        gather_kernel<<<blocks, 256>>>((const float4*)xa, (float4*)out, N, Cv);
    }
}

// round 17
// speedup vs baseline: 1.0251x; 1.0251x over previous
#include <cuda_runtime.h>
#include <stdint.h>

// ---------------------------------------------------------------------------
// AdaptiveUnpooling v17 (= v15 edge/scatter + miss-list-free gather):
//   - edge: 64-bit canonical CAS, 32MB table, UB=4, SMEM presence bitmap,
//     packed dual counter (present<<16 | total), POS payload in g_adj,
//     lb(256,6), exact-wave 888-block grid. Edge is at the chip atomic-rate
//     floor (~2.2M atomics @ ~27/cyc) — config frozen.
//   - gather: one warp per node over all N; present warps exit uniformly on
//     one broadcast bitmap load; two parallel adjacency chains; one store.
//   - pre-edge fork: side (clear_small -> scatter) || main clear_table,
//     joined BEFORE edge (nothing ever co-runs with edge).
// ---------------------------------------------------------------------------

#define TAB_BITS 22
#define TAB_SIZE (1u << TAB_BITS)      // 4M slots * 8B = 32MB (L2-resident)
#define MAX_N    131072
#define BM_WORDS (MAX_N / 32)
#define ADJ_DEG  96
#define UB       4
#define EDGE_BLOCKS  888               // 148 SMs * 6 blocks/SM
#define EDGE_THREADS 256

__device__ unsigned long long g_hash[TAB_SIZE];
__device__ unsigned g_cnt[MAX_N];      // (present_cnt << 16) | total_cnt
__device__ int g_pos[MAX_N];
__device__ unsigned g_bitmap[BM_WORDS];
__device__ int g_adj[MAX_N * ADJ_DEG]; // dense present-source POS values

__device__ __forceinline__ uint64_t mix64(uint64_t x) {
    x ^= x >> 33; x *= 0xff51afd7ed558ccdULL;
    x ^= x >> 33; x *= 0xc4ceb9fe1a85ec53ULL;
    x ^= x >> 33;
    return x;
}

__global__ void clear_table_kernel() {
    const int stride = gridDim.x * blockDim.x;
    const int tid = blockIdx.x * blockDim.x + threadIdx.x;
    ulonglong2* h2 = reinterpret_cast<ulonglong2*>(g_hash);
    for (unsigned i = tid; i < TAB_SIZE / 2; i += stride)
        h2[i] = make_ulonglong2(0ULL, 0ULL);
}

__global__ void clear_small_kernel(int N) {
    const int stride = gridDim.x * blockDim.x;
    const int tid = blockIdx.x * blockDim.x + threadIdx.x;
    for (int i = tid; i < N; i += stride) { g_cnt[i] = 0u; g_pos[i] = -1; }
    for (int i = tid; i < BM_WORDS; i += stride) g_bitmap[i] = 0u;
}

// Copy present rows, build pos map and presence bitmap.
__global__ void scatter_kernel(const float4* __restrict__ x4,
                               const int* __restrict__ perm,
                               float4* __restrict__ out4,
                               int P, int Cv) {
    const int gtid = blockIdx.x * blockDim.x + threadIdx.x;
    const int r = gtid / Cv;
    const int c = gtid - r * Cv;
    if (r < P) {
        const int node = perm[r];
        if (c == 0) {
            g_pos[node] = r;
            atomicOr(&g_bitmap[node >> 5], 1u << (node & 31));
        }
        out4[(size_t)node * Cv + c] = x4[(size_t)r * Cv + c];
    }
}

// UB edges per batch; SMEM bitmap presence; packed-counter adjacency alloc.
__global__ void __launch_bounds__(EDGE_THREADS, 6)
edge_kernel(const int* __restrict__ e0,
            const int* __restrict__ e1,
            int E, int N) {
    __shared__ unsigned s_bm[BM_WORDS];
    const int nw = (N + 31) >> 5;
    for (int i = threadIdx.x; i < nw; i += blockDim.x) s_bm[i] = g_bitmap[i];
    __syncthreads();

    const int tid = blockIdx.x * blockDim.x + threadIdx.x;
    const int TOT = gridDim.x * blockDim.x;
    const int step = TOT * UB;

    for (int base = tid; base < E; base += step) {
        int a[UB], b[UB];
        bool act[UB], ma[UB], mb[UB];

        // Phase 1: coalesced edge loads
        #pragma unroll
        for (int k = 0; k < UB; k++) {
            const int j = base + k * TOT;
            const bool v = (j < E);
            act[k] = v;
            a[k] = v ? e0[j] : 0;
            b[k] = v ? e1[j] : 1;
        }

        // Phase 2: presence checks from SMEM bitmap
        #pragma unroll
        for (int k = 0; k < UB; k++) {
            ma[k] = !((s_bm[a[k] >> 5] >> (a[k] & 31)) & 1u);
            mb[k] = !((s_bm[b[k] >> 5] >> (b[k] & 31)) & 1u);
            act[k] = act[k] && (a[k] != b[k]) && (ma[k] || mb[k]);
        }

        // Phase 3: canonical keys + batched first-probe CAS
        unsigned h[UB];
        unsigned long long old[UB];
        #pragma unroll
        for (int k = 0; k < UB; k++) {
            const int lo = min(a[k], b[k]), hi = max(a[k], b[k]);
            const uint64_t key = (uint64_t)lo * (uint64_t)N + (uint64_t)hi + 1ULL;
            h[k] = (unsigned)mix64(key) & (TAB_SIZE - 1);
            old[k] = act[k] ? atomicCAS(&g_hash[h[k]], 0ULL, key) : 1ULL;
        }

        // Phase 4: resolve rare collisions
        bool win[UB];
        #pragma unroll
        for (int k = 0; k < UB; k++) {
            win[k] = false;
            if (act[k]) {
                const int lo = min(a[k], b[k]), hi = max(a[k], b[k]);
                const uint64_t key = (uint64_t)lo * (uint64_t)N + (uint64_t)hi + 1ULL;
                unsigned long long o = old[k];
                unsigned hh = h[k];
                while (o != 0ULL && o != key) {
                    hh = (hh + 1) & (TAB_SIZE - 1);
                    o = atomicCAS(&g_hash[hh], 0ULL, key);
                }
                win[k] = (o == 0ULL);
            }
        }

        // Phase 5: packed-counter bump; adj store (pos payload) only for
        // present sources.
        #pragma unroll
        for (int k = 0; k < UB; k++) {
            if (win[k]) {
                if (ma[k]) {
                    const bool pres = !mb[k];
                    const unsigned o = atomicAdd(&g_cnt[a[k]],
                                                 pres ? 0x10001u : 1u);
                    if (pres) {
                        const int slot = (int)(o >> 16);
                        if (slot < ADJ_DEG)
                            g_adj[a[k] * ADJ_DEG + slot] = g_pos[b[k]];
                    }
                }
                if (mb[k]) {
                    const bool pres = !ma[k];
                    const unsigned o = atomicAdd(&g_cnt[b[k]],
                                                 pres ? 0x10001u : 1u);
                    if (pres) {
                        const int slot = (int)(o >> 16);
                        if (slot < ADJ_DEG)
                            g_adj[b[k] * ADJ_DEG + slot] = g_pos[a[k]];
                    }
                }
            }
        }
    }
}

// One warp per node (all N). Present nodes exit uniformly after one broadcast
// bitmap load. Missing: two parallel adjacency chains over dense POS entries,
// register accumulate, single non-atomic store of the mean.
__global__ void gather_kernel(const float4* __restrict__ xa4,
                              float4* __restrict__ out4,
                              int N, int Cv) {
    const int lane = threadIdx.x & 31;
    const int li   = lane & 15;
    const int half = lane >> 4;
    const int t = (blockIdx.x * blockDim.x + threadIdx.x) >> 5;
    if (t >= N) return;
    if ((g_bitmap[t >> 5] >> (t & 31)) & 1u) return;   // present: uniform exit

    const unsigned cw = g_cnt[t];
    const int total = (int)(cw & 0xFFFFu);
    const int m     = min((int)(cw >> 16), ADJ_DEG);
    const int4* row = reinterpret_cast<const int4*>(&g_adj[t * ADJ_DEG]);

    float4 acc = make_float4(0.f, 0.f, 0.f, 0.f);
    for (int g = half; g * 4 < m; g += 2) {
        const int4 q = row[g];
        const int bse = g * 4;
        float4 v0 = xa4[(size_t)q.x * Cv + li];
        float4 v1 = make_float4(0.f,0.f,0.f,0.f), v2 = v1, v3 = v1;
        if (bse + 1 < m) v1 = xa4[(size_t)q.y * Cv + li];
        if (bse + 2 < m) v2 = xa4[(size_t)q.z * Cv + li];
        if (bse + 3 < m) v3 = xa4[(size_t)q.w * Cv + li];
        acc.x += (v0.x + v1.x) + (v2.x + v3.x);
        acc.y += (v0.y + v1.y) + (v2.y + v3.y);
        acc.z += (v0.z + v1.z) + (v2.z + v3.z);
        acc.w += (v0.w + v1.w) + (v2.w + v3.w);
    }

    acc.x += __shfl_xor_sync(0xffffffffu, acc.x, 16);
    acc.y += __shfl_xor_sync(0xffffffffu, acc.y, 16);
    acc.z += __shfl_xor_sync(0xffffffffu, acc.z, 16);
    acc.w += __shfl_xor_sync(0xffffffffu, acc.w, 16);

    if (half == 0) {
        const float inv = (total > 0) ? 1.0f / (float)total : 0.0f;
        acc.x *= inv; acc.y *= inv; acc.z *= inv; acc.w *= inv;
        out4[(size_t)t * Cv + li] = acc;
    }
}

extern "C" void kernel_launch(void* const* d_in, const int* in_sizes, int n_in,
                              void* d_out, int out_size) {
    const float* xa   = (const float*)d_in[0];   // [P, C] f32
    const int*   perm = (const int*)d_in[1];     // [P]
    const int*   ei   = (const int*)d_in[2];     // [2, E]
    (void)n_in;

    const int P  = in_sizes[1];
    const int C  = in_sizes[0] / P;              // 64
    const int Cv = C / 4;                        // 16
    const int E  = in_sizes[2] / 2;
    const int N  = out_size / C;                 // 100000
    float* out = (float*)d_out;

    // One-time host resources (no device memory).
    static cudaStream_t s1 = nullptr;
    static cudaEvent_t evFork = nullptr, evSide = nullptr;
    if (s1 == nullptr) {
        cudaStreamCreateWithFlags(&s1, cudaStreamNonBlocking);
        cudaEventCreateWithFlags(&evFork, cudaEventDisableTiming);
        cudaEventCreateWithFlags(&evSide, cudaEventDisableTiming);
    }

    // Fork: side chain (clear_small -> scatter) || main clear_table.
    // Joined BEFORE edge: nothing ever co-runs with the edge kernel.
    cudaEventRecord(evFork, 0);
    cudaStreamWaitEvent(s1, evFork, 0);

    clear_small_kernel<<<256, 256, 0, s1>>>(N);
    {
        const int work = P * Cv;
        scatter_kernel<<<(work + 255) / 256, 256, 0, s1>>>(
            (const float4*)xa, perm, (float4*)out, P, Cv);
    }
    cudaEventRecord(evSide, s1);

    clear_table_kernel<<<2048, 256>>>();

    cudaStreamWaitEvent(0, evSide, 0);
    edge_kernel<<<EDGE_BLOCKS, EDGE_THREADS>>>(ei, ei + E, E, N);

    {
        const long long work = (long long)N * 32;    // one warp per node
        const int blocks = (int)((work + 255) / 256);
        gather_kernel<<<blocks, 256>>>((const float4*)xa, (float4*)out, N, Cv);
    }
}